// round 2
// baseline (speedup 1.0000x reference)
#include <cuda_runtime.h>
#include <cuda_bf16.h>
#include <math.h>

// ---------------------------------------------------------------------------
// DistMultDecoder: out[e] = sigmoid( z[src_e] . (W + W^T) . z[dst_e] )
// Restructured:  Wsym = W + W^T ; Y = Z @ Wsym ; out[e] = sigmoid(dot(Y[src], Z[dst]))
// ---------------------------------------------------------------------------

#define HID 128
#define MAX_NODES 100000

// Scratch (allocation-free rule: __device__ globals)
__device__ float g_Wsym[HID * HID];
__device__ float g_Y[(size_t)MAX_NODES * HID];
__device__ int   g_is64;   // 1 if edge_index stored as int64, 0 if int32

// ---------------- kernel 0: detect index dtype (int64 vs int32) ------------
// int64 little-endian values < 2^31 have every odd 32-bit word == 0.
__global__ void detect_kernel(const int* __restrict__ ei32) {
    if (threadIdx.x == 0) {
        int s = 0;
        #pragma unroll
        for (int i = 1; i < 64; i += 2) s |= ei32[i];
        g_is64 = (s == 0) ? 1 : 0;
    }
}

// --------------------------- kernel 1: symmetrize ---------------------------
__global__ void symm_kernel(const float* __restrict__ W) {
    int i = blockIdx.x * blockDim.x + threadIdx.x;   // 0..16383
    int r = i >> 7, c = i & 127;
    g_Wsym[i] = W[i] + W[c * HID + r];
}

// --------------------------- kernel 2: Y = Z @ Wsym -------------------------
// Block: 256 threads, 64 rows x 128 cols tile, full K=128.
// smem: Wsh 128x128 f32 (64KB) + Zsh 64x128 f32 (32KB) = 96KB dynamic.
__global__ __launch_bounds__(256) void gemm_kernel(const float* __restrict__ Z, int nrows) {
    extern __shared__ float sh[];
    float4* Wshv = (float4*)sh;                 // [128][32] float4
    float4* Zshv = (float4*)(sh + HID * HID);   // [64][32] float4

    int tid = threadIdx.x;

    // Load Wsym (16384 floats = 4096 float4)
    const float4* Wv = (const float4*)g_Wsym;
    #pragma unroll
    for (int i = 0; i < 16; i++) Wshv[tid + 256 * i] = Wv[tid + 256 * i];

    // Load Z tile (64 rows x 32 float4), guard tail block
    int row0 = blockIdx.x * 64;
    const float4* Zv = (const float4*)Z;
    #pragma unroll
    for (int i = 0; i < 8; i++) {
        int idx = tid + 256 * i;                 // < 2048
        int row = row0 + (idx >> 5);
        Zshv[idx] = (row < nrows) ? Zv[(size_t)row * 32 + (idx & 31)]
                                  : make_float4(0.f, 0.f, 0.f, 0.f);
    }
    __syncthreads();

    int tc = tid & 31;
    int tr = tid >> 5;

    float acc[8][4];
    #pragma unroll
    for (int i = 0; i < 8; i++)
        #pragma unroll
        for (int c = 0; c < 4; c++) acc[i][c] = 0.f;

    #pragma unroll 2
    for (int k = 0; k < HID; k += 4) {
        float4 w0 = Wshv[(k + 0) * 32 + tc];
        float4 w1 = Wshv[(k + 1) * 32 + tc];
        float4 w2 = Wshv[(k + 2) * 32 + tc];
        float4 w3 = Wshv[(k + 3) * 32 + tc];
        #pragma unroll
        for (int i = 0; i < 8; i++) {
            float4 zv = Zshv[(tr * 8 + i) * 32 + (k >> 2)];   // warp-uniform broadcast
            acc[i][0] += zv.x * w0.x + zv.y * w1.x + zv.z * w2.x + zv.w * w3.x;
            acc[i][1] += zv.x * w0.y + zv.y * w1.y + zv.z * w2.y + zv.w * w3.y;
            acc[i][2] += zv.x * w0.z + zv.y * w1.z + zv.z * w2.z + zv.w * w3.z;
            acc[i][3] += zv.x * w0.w + zv.y * w1.w + zv.z * w2.w + zv.w * w3.w;
        }
    }

    #pragma unroll
    for (int i = 0; i < 8; i++) {
        int row = row0 + tr * 8 + i;
        if (row < nrows) {
            float4 v = make_float4(acc[i][0], acc[i][1], acc[i][2], acc[i][3]);
            *((float4*)(g_Y + (size_t)row * HID + tc * 4)) = v;
        }
    }
}

// ------------------- kernel 3: per-edge gather + dot + sigmoid --------------
// Warp per edge: lane l loads float4 l of Y[src] and Z[dst], shfl-reduce.
__global__ __launch_bounds__(256) void edge_kernel(const void* __restrict__ ei,
                                                   const float* __restrict__ Z,
                                                   float* __restrict__ out, int E) {
    int gtid = blockIdx.x * blockDim.x + threadIdx.x;
    int e = gtid >> 5;
    int lane = gtid & 31;
    if (e >= E) return;

    long long src, dst;
    if (g_is64) {
        const long long* p = (const long long*)ei;
        src = p[e];
        dst = p[(size_t)E + e];
    } else {
        const int* p = (const int*)ei;
        src = p[e];
        dst = p[(size_t)E + e];
    }

    float4 a = ((const float4*)(g_Y + (size_t)src * HID))[lane];
    float4 b = ((const float4*)(Z + (size_t)dst * HID))[lane];

    float v = a.x * b.x + a.y * b.y + a.z * b.z + a.w * b.w;
    #pragma unroll
    for (int o = 16; o > 0; o >>= 1) v += __shfl_xor_sync(0xFFFFFFFFu, v, o);

    if (lane == 0) {
        out[e] = 1.0f / (1.0f + expf(-v));   // expf(+inf)->inf -> 0 : correct saturation
    }
}

// ---------------------------------------------------------------------------
extern "C" void kernel_launch(void* const* d_in, const int* in_sizes, int n_in,
                              void* d_out, int out_size) {
    // Robust input mapping by element count (don't trust positional order):
    //   W: 128*128 = 16384 ; z: N*128 (largest) ; edge_index: the remaining one.
    const float* z  = nullptr; int zsz = 0;
    const float* W  = nullptr;
    const void*  ei = nullptr; int eisz = 0;

    int wi = -1;
    for (int i = 0; i < n_in; i++) if (in_sizes[i] == HID * HID) { wi = i; break; }
    int zi = -1;
    for (int i = 0; i < n_in; i++) {
        if (i == wi) continue;
        if (zi < 0 || in_sizes[i] > in_sizes[zi]) zi = i;
    }
    int eii = -1;
    for (int i = 0; i < n_in; i++) if (i != wi && i != zi) { eii = i; break; }

    W    = (const float*)d_in[wi];
    z    = (const float*)d_in[zi];   zsz  = in_sizes[zi];
    ei   = d_in[eii];                eisz = in_sizes[eii];

    float* out = (float*)d_out;
    int nrows = zsz / HID;
    int E     = eisz / 2;

    // 0) detect index dtype
    detect_kernel<<<1, 32>>>((const int*)ei);

    // 1) Wsym = W + W^T
    symm_kernel<<<64, 256>>>(W);

    // 2) Y = Z @ Wsym  (96KB dynamic smem)
    int smem = (HID * HID + 64 * HID) * (int)sizeof(float);   // 98304
    cudaFuncSetAttribute(gemm_kernel, cudaFuncAttributeMaxDynamicSharedMemorySize, smem);
    int gblocks = (nrows + 63) / 64;
    gemm_kernel<<<gblocks, 256, smem>>>(z, nrows);

    // 3) edge scores: warp per edge, 8 edges per 256-thread block
    int eblocks = (E + 7) / 8;
    edge_kernel<<<eblocks, 256>>>(ei, z, out, E);
}

// round 3
// speedup vs baseline: 2.1270x; 2.1270x over previous
#include <cuda_runtime.h>
#include <cuda_bf16.h>
#include <math.h>

// ---------------------------------------------------------------------------
// DistMultDecoder: out[e] = sigmoid( z[src_e] . (W + W^T) . z[dst_e] )
// Restructured:  Wsym = W + W^T ; Y = Z @ Wsym ; out[e] = sigmoid(dot(Y[src], Z[dst]))
// ---------------------------------------------------------------------------

#define HID 128
#define MAX_NODES 100000

__device__ float g_Wsym[HID * HID];
__device__ float g_Y[(size_t)MAX_NODES * HID];
__device__ int   g_is64;   // 1 if edge_index stored as int64, 0 if int32

// ---------------- kernel 0: detect index dtype (int64 vs int32) ------------
__global__ void detect_kernel(const int* __restrict__ ei32) {
    if (threadIdx.x == 0) {
        int s = 0;
        #pragma unroll
        for (int i = 1; i < 64; i += 2) s |= ei32[i];
        g_is64 = (s == 0) ? 1 : 0;
    }
}

// --------------------------- kernel 1: symmetrize ---------------------------
__global__ void symm_kernel(const float* __restrict__ W) {
    int i = blockIdx.x * blockDim.x + threadIdx.x;   // 0..16383
    int r = i >> 7, c = i & 127;
    g_Wsym[i] = W[i] + W[c * HID + r];
}

// --------------------------- kernel 2: Y = Z @ Wsym -------------------------
__global__ __launch_bounds__(256) void gemm_kernel(const float* __restrict__ Z, int nrows) {
    extern __shared__ float sh[];
    float4* Wshv = (float4*)sh;                 // [128][32] float4
    float4* Zshv = (float4*)(sh + HID * HID);   // [64][32] float4

    int tid = threadIdx.x;

    const float4* Wv = (const float4*)g_Wsym;
    #pragma unroll
    for (int i = 0; i < 16; i++) Wshv[tid + 256 * i] = Wv[tid + 256 * i];

    int row0 = blockIdx.x * 64;
    const float4* Zv = (const float4*)Z;
    #pragma unroll
    for (int i = 0; i < 8; i++) {
        int idx = tid + 256 * i;
        int row = row0 + (idx >> 5);
        Zshv[idx] = (row < nrows) ? Zv[(size_t)row * 32 + (idx & 31)]
                                  : make_float4(0.f, 0.f, 0.f, 0.f);
    }
    __syncthreads();

    int tc = tid & 31;
    int tr = tid >> 5;

    float acc[8][4];
    #pragma unroll
    for (int i = 0; i < 8; i++)
        #pragma unroll
        for (int c = 0; c < 4; c++) acc[i][c] = 0.f;

    #pragma unroll 2
    for (int k = 0; k < HID; k += 4) {
        float4 w0 = Wshv[(k + 0) * 32 + tc];
        float4 w1 = Wshv[(k + 1) * 32 + tc];
        float4 w2 = Wshv[(k + 2) * 32 + tc];
        float4 w3 = Wshv[(k + 3) * 32 + tc];
        #pragma unroll
        for (int i = 0; i < 8; i++) {
            float4 zv = Zshv[(tr * 8 + i) * 32 + (k >> 2)];   // warp-uniform broadcast
            acc[i][0] += zv.x * w0.x + zv.y * w1.x + zv.z * w2.x + zv.w * w3.x;
            acc[i][1] += zv.x * w0.y + zv.y * w1.y + zv.z * w2.y + zv.w * w3.y;
            acc[i][2] += zv.x * w0.z + zv.y * w1.z + zv.z * w2.z + zv.w * w3.z;
            acc[i][3] += zv.x * w0.w + zv.y * w1.w + zv.z * w2.w + zv.w * w3.w;
        }
    }

    #pragma unroll
    for (int i = 0; i < 8; i++) {
        int row = row0 + tr * 8 + i;
        if (row < nrows) {
            float4 v = make_float4(acc[i][0], acc[i][1], acc[i][2], acc[i][3]);
            *((float4*)(g_Y + (size_t)row * HID + tc * 4)) = v;
        }
    }
}

// ------------------- kernel 3: per-edge gather + dot + sigmoid --------------
// 8 lanes per edge, 4 edges per warp.  Each lane issues 8 independent LDG.128
// (4 chunks of Y[src] + 4 chunks of Z[dst]) -> MLP=8, coalesced 128B lines.
// Reduction: 3 shfl-xor levels within 8-lane groups (4 edges reduced at once).
__global__ __launch_bounds__(256) void edge_kernel(const void* __restrict__ ei,
                                                   const float* __restrict__ Z,
                                                   float* __restrict__ out, int E) {
    const unsigned FULL = 0xFFFFFFFFu;
    int gtid  = blockIdx.x * blockDim.x + threadIdx.x;
    int warp  = gtid >> 5;
    int lane  = gtid & 31;
    int grp   = lane >> 3;       // 0..3  (edge within warp)
    int sub   = lane & 7;        // 0..7  (lane within edge-group)

    long long e0 = (long long)warp * 4;       // first edge of this warp
    if (e0 >= E) return;

    // --- batched index load: lanes 0..3 -> src[e0+l], lanes 4..7 -> dst[e0+l-4]
    long long myidx = 0;
    int is64 = g_is64;
    if (lane < 8) {
        long long e = e0 + (lane & 3);
        if (e >= E) e = 0;                                  // clamp (result unused)
        size_t off = (lane < 4) ? (size_t)e : (size_t)E + (size_t)e;
        if (is64) myidx = ((const long long*)ei)[off];
        else      myidx = ((const int*)ei)[off];
    }
    long long src = __shfl_sync(FULL, myidx, grp);
    long long dst = __shfl_sync(FULL, myidx, 4 + grp);

    const float4* Ya = (const float4*)(g_Y + (size_t)src * HID);
    const float4* Zb = (const float4*)(Z   + (size_t)dst * HID);

    // --- 8 independent vector loads per lane (full MLP) ---
    float4 a0 = Ya[sub];        float4 b0 = Zb[sub];
    float4 a1 = Ya[sub + 8];    float4 b1 = Zb[sub + 8];
    float4 a2 = Ya[sub + 16];   float4 b2 = Zb[sub + 16];
    float4 a3 = Ya[sub + 24];   float4 b3 = Zb[sub + 24];

    float v = a0.x * b0.x + a0.y * b0.y + a0.z * b0.z + a0.w * b0.w;
    v += a1.x * b1.x + a1.y * b1.y + a1.z * b1.z + a1.w * b1.w;
    v += a2.x * b2.x + a2.y * b2.y + a2.z * b2.z + a2.w * b2.w;
    v += a3.x * b3.x + a3.y * b3.y + a3.z * b3.z + a3.w * b3.w;

    // --- 3-level reduction within each 8-lane group ---
    v += __shfl_xor_sync(FULL, v, 1);
    v += __shfl_xor_sync(FULL, v, 2);
    v += __shfl_xor_sync(FULL, v, 4);

    // --- gather the 4 group sums to lanes 0..3, coalesced store ---
    float vg = __shfl_sync(FULL, v, lane << 3);   // lane l reads lane l*8 (lanes 0..3 valid)
    if (lane < 4) {
        long long e = e0 + lane;
        if (e < E) out[e] = 1.0f / (1.0f + expf(-vg));
    }
}

// ---------------------------------------------------------------------------
extern "C" void kernel_launch(void* const* d_in, const int* in_sizes, int n_in,
                              void* d_out, int out_size) {
    // Map inputs by element count: W = 16384; z = largest; edge_index = the rest.
    int wi = -1;
    for (int i = 0; i < n_in; i++) if (in_sizes[i] == HID * HID) { wi = i; break; }
    int zi = -1;
    for (int i = 0; i < n_in; i++) {
        if (i == wi) continue;
        if (zi < 0 || in_sizes[i] > in_sizes[zi]) zi = i;
    }
    int eii = -1;
    for (int i = 0; i < n_in; i++) if (i != wi && i != zi) { eii = i; break; }

    const float* W  = (const float*)d_in[wi];
    const float* z  = (const float*)d_in[zi];
    const void*  ei = d_in[eii];

    float* out = (float*)d_out;
    int nrows = in_sizes[zi] / HID;
    int E     = in_sizes[eii] / 2;

    detect_kernel<<<1, 32>>>((const int*)ei);
    symm_kernel<<<64, 256>>>(W);

    int smem = (HID * HID + 64 * HID) * (int)sizeof(float);   // 98304
    cudaFuncSetAttribute(gemm_kernel, cudaFuncAttributeMaxDynamicSharedMemorySize, smem);
    int gblocks = (nrows + 63) / 64;
    gemm_kernel<<<gblocks, 256, smem>>>(z, nrows);

    // 32 edges per 256-thread block (4 edges per warp)
    int eblocks = (E + 31) / 32;
    edge_kernel<<<eblocks, 256>>>(ei, z, out, E);
}

// round 5
// speedup vs baseline: 2.5920x; 1.2186x over previous
#include <cuda_runtime.h>
#include <cuda_bf16.h>
#include <math.h>
#include <stdint.h>

// ---------------------------------------------------------------------------
// DistMultDecoder: out[e] = sigmoid( z[src_e] . (W + W^T) . z[dst_e] )
//   Wsym = W + W^T (symmetric) ; Y = Z @ Wsym ; out[e] = sigmoid(dot(Y[src], Z[dst]))
// GEMM via warp-level mma.sync bf16 (sm_80 PTX, works on compute_103) with
// 2-term Dekker split:  Y = Zh*Wh + Zh*Wl + Zl*Wh   (fp32 accumulate)
// ---------------------------------------------------------------------------

#define HID 128
#define MAX_NODES 100000
#define PAD_W 68   // words per smem row = 136 bf16 (128 + 8 pad) -> conflict-free frags

__device__ float g_Y[(size_t)MAX_NODES * HID];
__device__ int   g_is64;
__device__ __nv_bfloat16 g_Wh[HID * HID];   // Wsym hi, row-major [n][k]
__device__ __nv_bfloat16 g_Wl[HID * HID];   // Wsym lo

// ---------------- kernel 0: detect index dtype (int64 vs int32) ------------
__global__ void detect_kernel(const int* __restrict__ ei32) {
    if (threadIdx.x == 0) {
        int s = 0;
        #pragma unroll
        for (int i = 1; i < 64; i += 2) s |= ei32[i];
        g_is64 = (s == 0) ? 1 : 0;
    }
}

// ---------------- kernel 1: Wsym = W + W^T -> bf16 hi/lo --------------------
__global__ void symm_kernel(const float* __restrict__ W) {
    int i = blockIdx.x * blockDim.x + threadIdx.x;   // 0..16383
    int n = i >> 7, k = i & 127;
    float v = W[n * HID + k] + W[k * HID + n];       // Wsym[n][k]
    __nv_bfloat16 hi = __float2bfloat16(v);
    __nv_bfloat16 lo = __float2bfloat16(v - __bfloat162float(hi));
    g_Wh[i] = hi;
    g_Wl[i] = lo;
}

// ---------------- kernel 2: Y = Z @ Wsym via mma.sync bf16 ------------------
#define MMA16816(D, A0, A1, A2, A3, B0, B1)                                   \
    asm volatile("mma.sync.aligned.m16n8k16.row.col.f32.bf16.bf16.f32 "       \
                 "{%0,%1,%2,%3}, {%4,%5,%6,%7}, {%8,%9}, {%0,%1,%2,%3};"      \
                 : "+f"(D[0]), "+f"(D[1]), "+f"(D[2]), "+f"(D[3])             \
                 : "r"(A0), "r"(A1), "r"(A2), "r"(A3), "r"(B0), "r"(B1))

__global__ __launch_bounds__(256) void gemm_mma_kernel(const float* __restrict__ Z, int nrows) {
    extern __shared__ __align__(16) uint32_t sh[];
    uint32_t* AH = sh;                      // 128 x 68 words (bf16x2)
    uint32_t* AL = sh + 128 * PAD_W;
    uint32_t* WH = sh + 2 * 128 * PAD_W;
    uint32_t* WL = sh + 3 * 128 * PAD_W;

    int tid = threadIdx.x;

    // ---- stage Wsym hi/lo into padded smem (8192 words each) ----
    {
        const uint32_t* gwh = (const uint32_t*)g_Wh;
        const uint32_t* gwl = (const uint32_t*)g_Wl;
        #pragma unroll
        for (int i = 0; i < 32; i++) {
            int idx  = tid + 256 * i;        // 0..8191
            int row  = idx >> 6;             // 64 words (=128 bf16) per row
            int word = idx & 63;
            WH[row * PAD_W + word] = gwh[idx];
            WL[row * PAD_W + word] = gwl[idx];
        }
    }

    // ---- load Z tile, split to bf16 hi/lo in smem ----
    {
        int row  = tid >> 1;
        int c0   = (tid & 1) * 64;
        int grow = blockIdx.x * 128 + row;
        bool valid = (grow < nrows);
        const float4* zr = (const float4*)(Z + (size_t)(valid ? grow : 0) * HID + c0);
        #pragma unroll
        for (int j = 0; j < 16; j++) {
            float4 v = zr[j];
            if (!valid) v = make_float4(0.f, 0.f, 0.f, 0.f);
            __nv_bfloat162 h0 = __floats2bfloat162_rn(v.x, v.y);
            __nv_bfloat162 h1 = __floats2bfloat162_rn(v.z, v.w);
            __nv_bfloat162 l0 = __floats2bfloat162_rn(v.x - __bfloat162float(h0.x),
                                                      v.y - __bfloat162float(h0.y));
            __nv_bfloat162 l1 = __floats2bfloat162_rn(v.z - __bfloat162float(h1.x),
                                                      v.w - __bfloat162float(h1.y));
            int wofs = row * PAD_W + ((c0 + 4 * j) >> 1);
            AH[wofs]     = *(uint32_t*)&h0;
            AH[wofs + 1] = *(uint32_t*)&h1;
            AL[wofs]     = *(uint32_t*)&l0;
            AL[wofs + 1] = *(uint32_t*)&l1;
        }
    }
    __syncthreads();

    // ---- warp tiling: warp = 32 rows x 64 cols = 2 x 8 (m16n8k16) tiles ----
    int lane = tid & 31, w = tid >> 5;
    int g = lane >> 2, t = lane & 3;
    int r0 = (w & 3) * 32;        // warp row base within CTA tile
    int n0 = (w >> 2) * 64;       // warp col base

    float d[2][8][4];
    #pragma unroll
    for (int m = 0; m < 2; m++)
        #pragma unroll
        for (int n = 0; n < 8; n++)
            #pragma unroll
            for (int q = 0; q < 4; q++) d[m][n][q] = 0.f;

    #pragma unroll 2
    for (int ks = 0; ks < 8; ks++) {
        int kb = ks * 8 + t;
        uint32_t ah[2][4], al[2][4];
        #pragma unroll
        for (int m = 0; m < 2; m++) {
            int rb = (r0 + 16 * m + g) * PAD_W + kb;
            ah[m][0] = AH[rb];              ah[m][1] = AH[rb + 8 * PAD_W];
            ah[m][2] = AH[rb + 4];          ah[m][3] = AH[rb + 8 * PAD_W + 4];
            al[m][0] = AL[rb];              al[m][1] = AL[rb + 8 * PAD_W];
            al[m][2] = AL[rb + 4];          al[m][3] = AL[rb + 8 * PAD_W + 4];
        }
        #pragma unroll
        for (int n = 0; n < 8; n++) {
            int nb = (n0 + 8 * n + g) * PAD_W + kb;
            uint32_t bh0 = WH[nb], bh1 = WH[nb + 4];
            uint32_t bl0 = WL[nb], bl1 = WL[nb + 4];
            #pragma unroll
            for (int m = 0; m < 2; m++) {
                MMA16816(d[m][n], ah[m][0], ah[m][1], ah[m][2], ah[m][3], bh0, bh1);
                MMA16816(d[m][n], ah[m][0], ah[m][1], ah[m][2], ah[m][3], bl0, bl1);
                MMA16816(d[m][n], al[m][0], al[m][1], al[m][2], al[m][3], bh0, bh1);
            }
        }
    }

    // ---- epilogue: d(m16n8 layout) -> g_Y ----
    int rowbase = blockIdx.x * 128 + r0 + g;
    #pragma unroll
    for (int m = 0; m < 2; m++) {
        int r = rowbase + 16 * m;
        #pragma unroll
        for (int n = 0; n < 8; n++) {
            int c = n0 + 8 * n + 2 * t;
            if (r < nrows)
                *(float2*)(g_Y + (size_t)r * HID + c) = make_float2(d[m][n][0], d[m][n][1]);
            if (r + 8 < nrows)
                *(float2*)(g_Y + (size_t)(r + 8) * HID + c) = make_float2(d[m][n][2], d[m][n][3]);
        }
    }
}

// ------------------- kernel 3: per-edge gather + dot + sigmoid --------------
__global__ __launch_bounds__(256) void edge_kernel(const void* __restrict__ ei,
                                                   const float* __restrict__ Z,
                                                   float* __restrict__ out, int E) {
    const unsigned FULL = 0xFFFFFFFFu;
    int gtid  = blockIdx.x * blockDim.x + threadIdx.x;
    int warp  = gtid >> 5;
    int lane  = gtid & 31;
    int grp   = lane >> 3;
    int sub   = lane & 7;

    long long e0 = (long long)warp * 4;
    if (e0 >= E) return;

    long long myidx = 0;
    int is64 = g_is64;
    if (lane < 8) {
        long long e = e0 + (lane & 3);
        if (e >= E) e = 0;
        size_t off = (lane < 4) ? (size_t)e : (size_t)E + (size_t)e;
        if (is64) myidx = ((const long long*)ei)[off];
        else      myidx = ((const int*)ei)[off];
    }
    long long src = __shfl_sync(FULL, myidx, grp);
    long long dst = __shfl_sync(FULL, myidx, 4 + grp);

    const float4* Ya = (const float4*)(g_Y + (size_t)src * HID);
    const float4* Zb = (const float4*)(Z   + (size_t)dst * HID);

    float4 a0 = Ya[sub];        float4 b0 = Zb[sub];
    float4 a1 = Ya[sub + 8];    float4 b1 = Zb[sub + 8];
    float4 a2 = Ya[sub + 16];   float4 b2 = Zb[sub + 16];
    float4 a3 = Ya[sub + 24];   float4 b3 = Zb[sub + 24];

    float v = a0.x * b0.x + a0.y * b0.y + a0.z * b0.z + a0.w * b0.w;
    v += a1.x * b1.x + a1.y * b1.y + a1.z * b1.z + a1.w * b1.w;
    v += a2.x * b2.x + a2.y * b2.y + a2.z * b2.z + a2.w * b2.w;
    v += a3.x * b3.x + a3.y * b3.y + a3.z * b3.z + a3.w * b3.w;

    v += __shfl_xor_sync(FULL, v, 1);
    v += __shfl_xor_sync(FULL, v, 2);
    v += __shfl_xor_sync(FULL, v, 4);

    float vg = __shfl_sync(FULL, v, lane << 3);
    if (lane < 4) {
        long long e = e0 + lane;
        if (e < E) out[e] = 1.0f / (1.0f + expf(-vg));
    }
}

// ---------------------------------------------------------------------------
extern "C" void kernel_launch(void* const* d_in, const int* in_sizes, int n_in,
                              void* d_out, int out_size) {
    // Map inputs by element count: W = 16384; z = largest; edge_index = the rest.
    int wi = -1;
    for (int i = 0; i < n_in; i++) if (in_sizes[i] == HID * HID) { wi = i; break; }
    int zi = -1;
    for (int i = 0; i < n_in; i++) {
        if (i == wi) continue;
        if (zi < 0 || in_sizes[i] > in_sizes[zi]) zi = i;
    }
    int eii = -1;
    for (int i = 0; i < n_in; i++) if (i != wi && i != zi) { eii = i; break; }

    const float* W  = (const float*)d_in[wi];
    const float* z  = (const float*)d_in[zi];
    const void*  ei = d_in[eii];

    float* out = (float*)d_out;
    int nrows = in_sizes[zi] / HID;
    int E     = in_sizes[eii] / 2;

    detect_kernel<<<1, 32>>>((const int*)ei);
    symm_kernel<<<64, 256>>>(W);

    int smem = 4 * 128 * PAD_W * (int)sizeof(uint32_t);   // 139264 B
    cudaFuncSetAttribute(gemm_mma_kernel, cudaFuncAttributeMaxDynamicSharedMemorySize, smem);
    int gblocks = (nrows + 127) / 128;
    gemm_mma_kernel<<<gblocks, 256, smem>>>(z, nrows);

    int eblocks = (E + 31) / 32;
    edge_kernel<<<eblocks, 256>>>(ei, z, out, E);
}